// round 3
// baseline (speedup 1.0000x reference)
#include <cuda_runtime.h>
#include <cooperative_groups.h>
#include <math.h>

namespace cg = cooperative_groups;

#define B_   256
#define T_   256
#define D_   128
#define H_   256
#define R_   (B_ * T_)        // 65536 rows (b,t)
#define KU   384              // packed input width: [x_imp(128), m(128), Delta(128)]
#define CW   1024             // packed output width: [A_z(256), A_r(256), A_h(256), dh(256)]
#define NB   8                // batches per cluster
#define WPAD 260              // padded k-stride in recurrence smem (bank spread: 260%32==4)

// ---------------- scratch (static device allocations; no runtime alloc) ----------------
__device__ float g_U[(size_t)R_ * KU];       // 96 MB  packed inputs
__device__ float g_S[(size_t)R_ * CW];       // 256 MB precomputed, layout [t][b][CW]
__device__ float g_Wp[CW * KU];              // packed precompute weights [col][k]
__device__ float g_bp[CW];                   // packed biases
__device__ float g_WT[3 * H_ * H_];          // recurrent weights [g][j][k] = W_g[j][128+k]
__device__ float g_Hfin[B_ * H_];            // final hidden state

__device__ __forceinline__ float sigf(float x) { return 1.f / (1.f + expf(-x)); }

// ---------------- kernel 0: pack weights ----------------
__global__ void pack_kernel(const float* __restrict__ Wz, const float* __restrict__ bz,
                            const float* __restrict__ Wr, const float* __restrict__ br,
                            const float* __restrict__ Wh, const float* __restrict__ bh,
                            const float* __restrict__ Wgh, const float* __restrict__ bgh) {
    int idx = blockIdx.x * blockDim.x + threadIdx.x;
    if (idx < CW * KU) {
        int col = idx / KU, k = idx - col * KU;
        int g = col >> 8, j = col & 255;
        float v = 0.f;
        if (g < 3) {
            const float* W = (g == 0) ? Wz : ((g == 1) ? Wr : Wh);
            if (k < 128)      v = W[j * 512 + k];            // x part (comb cols 0..127)
            else if (k < 256) v = W[j * 512 + 256 + k];      // m part (comb cols 384..511)
        } else {
            if (k >= 256) v = Wgh[j * 128 + (k - 256)];      // Delta part
        }
        g_Wp[idx] = v;
    }
    if (idx < CW) {
        int g = idx >> 8, j = idx & 255;
        g_bp[idx] = (g == 0) ? bz[j] : (g == 1) ? br[j] : (g == 2) ? bh[j] : bgh[j];
    }
    if (idx < 3 * H_ * H_) {
        int g = idx >> 16;
        int rem = idx & 65535;
        int j = rem >> 8, k = rem & 255;
        const float* W = (g == 0) ? Wz : ((g == 1) ? Wr : Wh);
        g_WT[idx] = W[j * 512 + 128 + k];                    // h part (comb cols 128..383)
    }
}

// ---------------- kernel 1: imputation + input packing ----------------
__global__ void build_U(const float* __restrict__ inp, const float* __restrict__ Xmean,
                        const float* __restrict__ Wgx, const float* __restrict__ bgx) {
    int idx = blockIdx.x * blockDim.x + threadIdx.x;
    if (idx >= R_ * D_) return;
    int d = idx & 127;
    int r = idx >> 7;
    int t = r & 255;
    int b = r >> 8;
    size_t TD = (size_t)T_ * D_;
    size_t base = (size_t)b * 4 * TD + (size_t)t * D_ + d;
    float x  = inp[base];
    float xl = inp[base + TD];
    float m  = inp[base + 2 * TD];
    float dl = inp[base + 3 * TD];
    float a   = dl * Wgx[d * D_ + d] + bgx[d];
    float dxt = expf(-fmaxf(a, 0.f));
    if (isnan(x)) x = -1.f;
    float xi = m * x + (1.f - m) * (dxt * xl + (1.f - dxt) * Xmean[t * D_ + d]);
    float* Urow = g_U + (size_t)r * KU;
    Urow[d]       = xi;
    Urow[128 + d] = m;
    Urow[256 + d] = dl;
}

// ---------------- kernel 2: precompute GEMM  S = U @ Wp^T (+bias, dh activation) -------
// 128-row x 64-col tiles, 256 threads, 8x4 register blocking, k-major smem.
__global__ __launch_bounds__(256) void gemm_pre() {
    const int c0 = blockIdx.x * 64;     // col tile (gate-aligned)
    const int r0 = blockIdx.y * 128;    // row tile
    const int gate   = c0 >> 8;
    const int kstart = (gate < 3) ? 0 : 256;
    const int ktiles = (gate < 3) ? 8 : 4;
    __shared__ float As[32][132];       // [k][row]
    __shared__ float Bs[32][68];        // [k][col]
    const int tid = threadIdx.x;
    const int tx = tid & 15;            // col group (4 cols)
    const int ty = tid >> 4;            // row group (8 rows)
    const int rowA = tid & 127;
    const int koA  = (tid >> 7) * 16;
    const int rowB = tid & 63;
    const int koB  = (tid >> 6) * 8;

    float acc[8][4];
#pragma unroll
    for (int d = 0; d < 8; d++)
#pragma unroll
        for (int e = 0; e < 4; e++) acc[d][e] = 0.f;

    for (int kt = 0; kt < ktiles; kt++) {
        int kb = kstart + kt * 32;
        float4 av0 = *(const float4*)&g_U[(size_t)(r0 + rowA) * KU + kb + koA + 0];
        float4 av1 = *(const float4*)&g_U[(size_t)(r0 + rowA) * KU + kb + koA + 4];
        float4 av2 = *(const float4*)&g_U[(size_t)(r0 + rowA) * KU + kb + koA + 8];
        float4 av3 = *(const float4*)&g_U[(size_t)(r0 + rowA) * KU + kb + koA + 12];
        float4 bv0 = *(const float4*)&g_Wp[(size_t)(c0 + rowB) * KU + kb + koB + 0];
        float4 bv1 = *(const float4*)&g_Wp[(size_t)(c0 + rowB) * KU + kb + koB + 4];
        __syncthreads();
        As[koA + 0][rowA] = av0.x;  As[koA + 1][rowA] = av0.y;
        As[koA + 2][rowA] = av0.z;  As[koA + 3][rowA] = av0.w;
        As[koA + 4][rowA] = av1.x;  As[koA + 5][rowA] = av1.y;
        As[koA + 6][rowA] = av1.z;  As[koA + 7][rowA] = av1.w;
        As[koA + 8][rowA] = av2.x;  As[koA + 9][rowA] = av2.y;
        As[koA +10][rowA] = av2.z;  As[koA +11][rowA] = av2.w;
        As[koA +12][rowA] = av3.x;  As[koA +13][rowA] = av3.y;
        As[koA +14][rowA] = av3.z;  As[koA +15][rowA] = av3.w;
        Bs[koB + 0][rowB] = bv0.x;  Bs[koB + 1][rowB] = bv0.y;
        Bs[koB + 2][rowB] = bv0.z;  Bs[koB + 3][rowB] = bv0.w;
        Bs[koB + 4][rowB] = bv1.x;  Bs[koB + 5][rowB] = bv1.y;
        Bs[koB + 6][rowB] = bv1.z;  Bs[koB + 7][rowB] = bv1.w;
        __syncthreads();
#pragma unroll 8
        for (int k = 0; k < 32; k++) {
            float4 a0 = *(const float4*)&As[k][ty * 8];
            float4 a1 = *(const float4*)&As[k][ty * 8 + 4];
            float4 bb = *(const float4*)&Bs[k][tx * 4];
            float ar[8] = {a0.x,a0.y,a0.z,a0.w,a1.x,a1.y,a1.z,a1.w};
            float br_[4] = {bb.x,bb.y,bb.z,bb.w};
#pragma unroll
            for (int d = 0; d < 8; d++)
#pragma unroll
                for (int e = 0; e < 4; e++)
                    acc[d][e] = fmaf(ar[d], br_[e], acc[d][e]);
        }
    }
    float4 bias = *(const float4*)&g_bp[c0 + tx * 4];
#pragma unroll
    for (int d = 0; d < 8; d++) {
        int row = r0 + ty * 8 + d;
        int bb  = row >> 8;          // batch
        int tt  = row & 255;         // time
        float4 v;
        v.x = acc[d][0] + bias.x;  v.y = acc[d][1] + bias.y;
        v.z = acc[d][2] + bias.z;  v.w = acc[d][3] + bias.w;
        if (gate == 3) {
            v.x = expf(-fmaxf(v.x, 0.f));  v.y = expf(-fmaxf(v.y, 0.f));
            v.z = expf(-fmaxf(v.z, 0.f));  v.w = expf(-fmaxf(v.w, 0.f));
        }
        *(float4*)&g_S[((size_t)tt * B_ + bb) * CW + c0 + tx * 4] = v;
    }
}

// ---------------- kernel 3: recurrence (4-CTA cluster, resident fp32 weights) ----------
// 512 threads. Thread tile: 1 j x 2 batches x k-half (shuffle-reduce over k split).
// Lane layout: bq = tid&3 (2 batches each), kh = (tid>>2)&1, jl = tid>>3.
__global__ void __cluster_dims__(4, 1, 1) __launch_bounds__(512, 1) recur_kernel() {
    extern __shared__ float smem[];
    float* Wq    = smem;                       // [3][64][WPAD]
    float* hbuf  = Wq + 3 * 64 * WPAD;         // [NB][WPAD]  layout [b][k]
    float* rhbuf = hbuf + NB * WPAD;           // [NB][WPAD]

    cg::cluster_group cluster = cg::this_cluster();
    const int rank = (int)cluster.block_rank();    // 0..3, owns j in [rank*64, rank*64+64)
    const int tid  = threadIdx.x;
    const int bq   = tid & 3;                      // batch pair 0..3
    const int kh   = (tid >> 2) & 1;               // k half
    const int jl   = tid >> 3;                     // 0..63
    const int b0   = bq * 2, b1 = bq * 2 + 1;
    const int jg   = rank * 64 + jl;
    const int k0   = kh * 128;
    const int b_base = (blockIdx.x >> 2) * NB;
    const int b_s  = tid >> 6;                     // scale role: batch 0..7
    const int k4s  = (tid & 63) * 4;               // scale role: k offset

    // Load this CTA's j-slice of the 3 recurrent matrices (float4, coalesced)
    for (int idx4 = tid; idx4 < 3 * 64 * 64; idx4 += 512) {
        int g  = idx4 >> 12;
        int jj = (idx4 >> 6) & 63;
        int kq = idx4 & 63;
        float4 v = *(const float4*)&g_WT[g * 65536 + (rank * 64 + jj) * 256 + kq * 4];
        *(float4*)&Wq[g * (64 * WPAD) + jj * WPAD + kq * 4] = v;
    }
    for (int i = tid; i < NB * WPAD; i += 512) { hbuf[i] = 0.f; rhbuf[i] = 0.f; }
    __syncthreads();
    cluster.sync();

    const float* wzp = Wq + jl * WPAD;
    const float* wrp = Wq + 64 * WPAD + jl * WPAD;
    const float* whp = Wq + 2 * 64 * WPAD + jl * WPAD;
    const float* h0p = hbuf + b0 * WPAD;
    const float* h1p = hbuf + b1 * WPAD;
    const float* p0p = rhbuf + b0 * WPAD;
    const float* p1p = rhbuf + b1 * WPAD;

    // preload t=0 S values
    size_t srow0 = ((size_t)0 * B_ + b_base + b0) * CW;
    size_t srow1 = ((size_t)0 * B_ + b_base + b1) * CW;
    float az0c = g_S[srow0 + jg],        az1c = g_S[srow1 + jg];
    float ar0c = g_S[srow0 + 256 + jg],  ar1c = g_S[srow1 + 256 + jg];
    float ah0c = g_S[srow0 + 512 + jg],  ah1c = g_S[srow1 + 512 + jg];
    float4 dhc = *(const float4*)&g_S[((size_t)0 * B_ + b_base + b_s) * CW + 768 + k4s];

    for (int t = 0; t < T_; t++) {
        // ---- scale h by delta_h (full local copy; vectorized, uses prefetched dh) ----
        {
            float4 hv = *(float4*)&hbuf[b_s * WPAD + k4s];
            hv.x *= dhc.x; hv.y *= dhc.y; hv.z *= dhc.z; hv.w *= dhc.w;
            *(float4*)&hbuf[b_s * WPAD + k4s] = hv;
        }
        __syncthreads();

        // ---- prefetch t+1 S values (latency hidden behind matvecs) ----
        int tn = (t + 1 < T_) ? t + 1 : t;
        size_t nrow0 = ((size_t)tn * B_ + b_base + b0) * CW;
        size_t nrow1 = ((size_t)tn * B_ + b_base + b1) * CW;
        float naz0 = g_S[nrow0 + jg],       naz1 = g_S[nrow1 + jg];
        float nar0 = g_S[nrow0 + 256 + jg], nar1 = g_S[nrow1 + 256 + jg];
        float nah0 = g_S[nrow0 + 512 + jg], nah1 = g_S[nrow1 + 512 + jg];
        float4 ndh = *(const float4*)&g_S[((size_t)tn * B_ + b_base + b_s) * CW + 768 + k4s];

        // ---- z / r matvecs over this thread's k-half ----
        float accz0 = 0.f, accz1 = 0.f, accr0 = 0.f, accr1 = 0.f;
#pragma unroll 8
        for (int kk = 0; kk < 128; kk += 4) {
            float4 wz = *(const float4*)&wzp[k0 + kk];
            float4 wr = *(const float4*)&wrp[k0 + kk];
            float4 h0 = *(const float4*)&h0p[k0 + kk];
            float4 h1 = *(const float4*)&h1p[k0 + kk];
            accz0 = fmaf(wz.x,h0.x, fmaf(wz.y,h0.y, fmaf(wz.z,h0.z, fmaf(wz.w,h0.w, accz0))));
            accz1 = fmaf(wz.x,h1.x, fmaf(wz.y,h1.y, fmaf(wz.z,h1.z, fmaf(wz.w,h1.w, accz1))));
            accr0 = fmaf(wr.x,h0.x, fmaf(wr.y,h0.y, fmaf(wr.z,h0.z, fmaf(wr.w,h0.w, accr0))));
            accr1 = fmaf(wr.x,h1.x, fmaf(wr.y,h1.y, fmaf(wr.z,h1.z, fmaf(wr.w,h1.w, accr1))));
        }
        accz0 += __shfl_xor_sync(0xffffffffu, accz0, 4);
        accz1 += __shfl_xor_sync(0xffffffffu, accz1, 4);
        accr0 += __shfl_xor_sync(0xffffffffu, accr0, 4);
        accr1 += __shfl_xor_sync(0xffffffffu, accr1, 4);
        float z0 = sigf(accz0 + az0c);
        float z1 = sigf(accz1 + az1c);
        float r0 = sigf(accr0 + ar0c);
        float r1 = sigf(accr1 + ar1c);

        float hj0 = h0p[jg];
        float hj1 = h1p[jg];
        if (kh == 0) {
            rhbuf[b0 * WPAD + jg] = r0 * hj0;
            rhbuf[b1 * WPAD + jg] = r1 * hj1;
        }
        __syncthreads();
        // push my contiguous j-quarter of rh to the 3 peers (float4 blocks)
        if (tid < 384) {
            int pr   = tid >> 7;                    // 0..2
            int peer = (rank + 1 + pr) & 3;
            int rem  = tid & 127;
            int bb   = rem >> 4;
            int v    = rem & 15;
            int off  = bb * WPAD + rank * 64 + v * 4;
            float4 val = *(float4*)&rhbuf[off];
            float* dst = cluster.map_shared_rank(rhbuf, peer);
            *(float4*)&dst[off] = val;
        }
        cluster.sync();

        // ---- h_tilde matvec over full r*h (this thread's k-half) ----
        float acch0 = 0.f, acch1 = 0.f;
#pragma unroll 8
        for (int kk = 0; kk < 128; kk += 4) {
            float4 wh = *(const float4*)&whp[k0 + kk];
            float4 p0 = *(const float4*)&p0p[k0 + kk];
            float4 p1 = *(const float4*)&p1p[k0 + kk];
            acch0 = fmaf(wh.x,p0.x, fmaf(wh.y,p0.y, fmaf(wh.z,p0.z, fmaf(wh.w,p0.w, acch0))));
            acch1 = fmaf(wh.x,p1.x, fmaf(wh.y,p1.y, fmaf(wh.z,p1.z, fmaf(wh.w,p1.w, acch1))));
        }
        acch0 += __shfl_xor_sync(0xffffffffu, acch0, 4);
        acch1 += __shfl_xor_sync(0xffffffffu, acch1, 4);
        float ht0 = tanhf(acch0 + ah0c);
        float ht1 = tanhf(acch1 + ah1c);
        float hn0 = (1.f - z0) * hj0 + z0 * ht0;
        float hn1 = (1.f - z1) * hj1 + z1 * ht1;
        if (kh == 0) {
            hbuf[b0 * WPAD + jg] = hn0;
            hbuf[b1 * WPAD + jg] = hn1;
        }
        __syncthreads();
        if (tid < 384) {
            int pr   = tid >> 7;
            int peer = (rank + 1 + pr) & 3;
            int rem  = tid & 127;
            int bb   = rem >> 4;
            int v    = rem & 15;
            int off  = bb * WPAD + rank * 64 + v * 4;
            float4 val = *(float4*)&hbuf[off];
            float* dst = cluster.map_shared_rank(hbuf, peer);
            *(float4*)&dst[off] = val;
        }
        cluster.sync();

        if (t == T_ - 1 && kh == 0) {
            g_Hfin[(b_base + b0) * H_ + jg] = hn0;
            g_Hfin[(b_base + b1) * H_ + jg] = hn1;
        }
        az0c = naz0; az1c = naz1; ar0c = nar0; ar1c = nar1;
        ah0c = nah0; ah1c = nah1; dhc = ndh;
    }
}

// ---------------- kernel 4: out = h_final @ W_out^T + b_out ----------------
__global__ void finalize_k(const float* __restrict__ Wout, const float* __restrict__ bout,
                           float* __restrict__ out) {
    int b = blockIdx.x;
    int tid = threadIdx.x;   // 64 threads
    float s = 0.f;
    for (int j = tid; j < H_; j += 64) s += g_Hfin[b * H_ + j] * Wout[j];
    __shared__ float red[64];
    red[tid] = s;
    __syncthreads();
    if (tid < 32) {
        float v = red[tid] + red[tid + 32];
#pragma unroll
        for (int o = 16; o; o >>= 1) v += __shfl_down_sync(0xffffffffu, v, o);
        if (tid == 0) out[b] = v + bout[0];
    }
}

// ---------------- host launcher ----------------
extern "C" void kernel_launch(void* const* d_in, const int* in_sizes, int n_in,
                              void* d_out, int out_size) {
    const float* inp   = (const float*)d_in[0];
    // d_in[1] = static_data (unused by the reference computation)
    const float* Xmean = (const float*)d_in[2];
    const float* Wz    = (const float*)d_in[3];
    const float* bz    = (const float*)d_in[4];
    const float* Wr    = (const float*)d_in[5];
    const float* br    = (const float*)d_in[6];
    const float* Wh    = (const float*)d_in[7];
    const float* bh    = (const float*)d_in[8];
    const float* Wgx   = (const float*)d_in[9];
    const float* bgx   = (const float*)d_in[10];
    const float* Wgh   = (const float*)d_in[11];
    const float* bgh   = (const float*)d_in[12];
    const float* Wout  = (const float*)d_in[13];
    const float* bout  = (const float*)d_in[14];
    float* out = (float*)d_out;

    pack_kernel<<<(CW * KU + 255) / 256, 256>>>(Wz, bz, Wr, br, Wh, bh, Wgh, bgh);
    build_U<<<(R_ * D_ + 255) / 256, 256>>>(inp, Xmean, Wgx, bgx);

    dim3 g2(CW / 64, R_ / 128);   // 16 x 512 tiles
    gemm_pre<<<g2, 256>>>();

    const int smemb = (3 * 64 * WPAD + 2 * NB * WPAD) * (int)sizeof(float);  // 216320 B
    cudaFuncSetAttribute(recur_kernel, cudaFuncAttributeMaxDynamicSharedMemorySize, smemb);
    recur_kernel<<<128, 512, smemb>>>();   // 32 clusters of 4 CTAs

    finalize_k<<<B_, 64>>>(Wout, bout, out);
}

// round 4
// speedup vs baseline: 1.5094x; 1.5094x over previous
#include <cuda_runtime.h>
#include <cooperative_groups.h>
#include <math.h>

namespace cg = cooperative_groups;

#define B_   256
#define T_   256
#define D_   128
#define H_   256
#define R_   (B_ * T_)        // 65536 rows (b,t)
#define KU   384              // packed input width: [x_imp(128), m(128), Delta(128)]
#define CW   1024             // packed output width: [A_z(256), A_r(256), A_h(256), dh(256)]
#define NB   8                // batches per cluster
#define WPAD 260              // padded k-stride in recurrence smem (260%32==4 -> conflict-free)

// ---------------- scratch (static device allocations; no runtime alloc) ----------------
__device__ float g_U[(size_t)R_ * KU];       // 96 MB  packed inputs
__device__ float g_S[(size_t)R_ * CW];       // 256 MB precomputed, layout [t][b][CW]
__device__ float g_Wp[CW * KU];              // packed precompute weights [col][k]
__device__ float g_bp[CW];                   // packed biases
__device__ float g_WT[3 * H_ * H_];          // recurrent weights [g][j][k] = W_g[j][128+k]
__device__ float g_Hfin[B_ * H_];            // final hidden state

__device__ __forceinline__ float sigf(float x) { return 1.f / (1.f + expf(-x)); }

// ---------------- kernel 0: pack weights ----------------
__global__ void pack_kernel(const float* __restrict__ Wz, const float* __restrict__ bz,
                            const float* __restrict__ Wr, const float* __restrict__ br,
                            const float* __restrict__ Wh, const float* __restrict__ bh,
                            const float* __restrict__ Wgh, const float* __restrict__ bgh) {
    int idx = blockIdx.x * blockDim.x + threadIdx.x;
    if (idx < CW * KU) {
        int col = idx / KU, k = idx - col * KU;
        int g = col >> 8, j = col & 255;
        float v = 0.f;
        if (g < 3) {
            const float* W = (g == 0) ? Wz : ((g == 1) ? Wr : Wh);
            if (k < 128)      v = W[j * 512 + k];            // x part (comb cols 0..127)
            else if (k < 256) v = W[j * 512 + 256 + k];      // m part (comb cols 384..511)
        } else {
            if (k >= 256) v = Wgh[j * 128 + (k - 256)];      // Delta part
        }
        g_Wp[idx] = v;
    }
    if (idx < CW) {
        int g = idx >> 8, j = idx & 255;
        g_bp[idx] = (g == 0) ? bz[j] : (g == 1) ? br[j] : (g == 2) ? bh[j] : bgh[j];
    }
    if (idx < 3 * H_ * H_) {
        int g = idx >> 16;
        int rem = idx & 65535;
        int j = rem >> 8, k = rem & 255;
        const float* W = (g == 0) ? Wz : ((g == 1) ? Wr : Wh);
        g_WT[idx] = W[j * 512 + 128 + k];                    // h part (comb cols 128..383)
    }
}

// ---------------- kernel 1: imputation + input packing ----------------
__global__ void build_U(const float* __restrict__ inp, const float* __restrict__ Xmean,
                        const float* __restrict__ Wgx, const float* __restrict__ bgx) {
    int idx = blockIdx.x * blockDim.x + threadIdx.x;
    if (idx >= R_ * D_) return;
    int d = idx & 127;
    int r = idx >> 7;
    int t = r & 255;
    int b = r >> 8;
    size_t TD = (size_t)T_ * D_;
    size_t base = (size_t)b * 4 * TD + (size_t)t * D_ + d;
    float x  = inp[base];
    float xl = inp[base + TD];
    float m  = inp[base + 2 * TD];
    float dl = inp[base + 3 * TD];
    float a   = dl * Wgx[d * D_ + d] + bgx[d];
    float dxt = expf(-fmaxf(a, 0.f));
    if (isnan(x)) x = -1.f;
    float xi = m * x + (1.f - m) * (dxt * xl + (1.f - dxt) * Xmean[t * D_ + d]);
    float* Urow = g_U + (size_t)r * KU;
    Urow[d]       = xi;
    Urow[128 + d] = m;
    Urow[256 + d] = dl;
}

// ---------------- kernel 2: precompute GEMM  S = U @ Wp^T (+bias, dh activation) -------
// 128-row x 64-col tiles, 256 threads, 8x4 register blocking, k-major smem.
__global__ __launch_bounds__(256) void gemm_pre() {
    const int c0 = blockIdx.x * 64;     // col tile (gate-aligned)
    const int r0 = blockIdx.y * 128;    // row tile
    const int gate   = c0 >> 8;
    const int kstart = (gate < 3) ? 0 : 256;
    const int ktiles = (gate < 3) ? 8 : 4;
    __shared__ float As[32][132];       // [k][row]
    __shared__ float Bs[32][68];        // [k][col]
    const int tid = threadIdx.x;
    const int tx = tid & 15;            // col group (4 cols)
    const int ty = tid >> 4;            // row group (8 rows)
    const int rowA = tid & 127;
    const int koA  = (tid >> 7) * 16;
    const int rowB = tid & 63;
    const int koB  = (tid >> 6) * 8;

    float acc[8][4];
#pragma unroll
    for (int d = 0; d < 8; d++)
#pragma unroll
        for (int e = 0; e < 4; e++) acc[d][e] = 0.f;

    for (int kt = 0; kt < ktiles; kt++) {
        int kb = kstart + kt * 32;
        float4 av0 = *(const float4*)&g_U[(size_t)(r0 + rowA) * KU + kb + koA + 0];
        float4 av1 = *(const float4*)&g_U[(size_t)(r0 + rowA) * KU + kb + koA + 4];
        float4 av2 = *(const float4*)&g_U[(size_t)(r0 + rowA) * KU + kb + koA + 8];
        float4 av3 = *(const float4*)&g_U[(size_t)(r0 + rowA) * KU + kb + koA + 12];
        float4 bv0 = *(const float4*)&g_Wp[(size_t)(c0 + rowB) * KU + kb + koB + 0];
        float4 bv1 = *(const float4*)&g_Wp[(size_t)(c0 + rowB) * KU + kb + koB + 4];
        __syncthreads();
        As[koA + 0][rowA] = av0.x;  As[koA + 1][rowA] = av0.y;
        As[koA + 2][rowA] = av0.z;  As[koA + 3][rowA] = av0.w;
        As[koA + 4][rowA] = av1.x;  As[koA + 5][rowA] = av1.y;
        As[koA + 6][rowA] = av1.z;  As[koA + 7][rowA] = av1.w;
        As[koA + 8][rowA] = av2.x;  As[koA + 9][rowA] = av2.y;
        As[koA +10][rowA] = av2.z;  As[koA +11][rowA] = av2.w;
        As[koA +12][rowA] = av3.x;  As[koA +13][rowA] = av3.y;
        As[koA +14][rowA] = av3.z;  As[koA +15][rowA] = av3.w;
        Bs[koB + 0][rowB] = bv0.x;  Bs[koB + 1][rowB] = bv0.y;
        Bs[koB + 2][rowB] = bv0.z;  Bs[koB + 3][rowB] = bv0.w;
        Bs[koB + 4][rowB] = bv1.x;  Bs[koB + 5][rowB] = bv1.y;
        Bs[koB + 6][rowB] = bv1.z;  Bs[koB + 7][rowB] = bv1.w;
        __syncthreads();
#pragma unroll 8
        for (int k = 0; k < 32; k++) {
            float4 a0 = *(const float4*)&As[k][ty * 8];
            float4 a1 = *(const float4*)&As[k][ty * 8 + 4];
            float4 bb = *(const float4*)&Bs[k][tx * 4];
            float ar[8] = {a0.x,a0.y,a0.z,a0.w,a1.x,a1.y,a1.z,a1.w};
            float br_[4] = {bb.x,bb.y,bb.z,bb.w};
#pragma unroll
            for (int d = 0; d < 8; d++)
#pragma unroll
                for (int e = 0; e < 4; e++)
                    acc[d][e] = fmaf(ar[d], br_[e], acc[d][e]);
        }
    }
    float4 bias = *(const float4*)&g_bp[c0 + tx * 4];
#pragma unroll
    for (int d = 0; d < 8; d++) {
        int row = r0 + ty * 8 + d;
        int bb  = row >> 8;          // batch
        int tt  = row & 255;         // time
        float4 v;
        v.x = acc[d][0] + bias.x;  v.y = acc[d][1] + bias.y;
        v.z = acc[d][2] + bias.z;  v.w = acc[d][3] + bias.w;
        if (gate == 3) {
            v.x = expf(-fmaxf(v.x, 0.f));  v.y = expf(-fmaxf(v.y, 0.f));
            v.z = expf(-fmaxf(v.z, 0.f));  v.w = expf(-fmaxf(v.w, 0.f));
        }
        *(float4*)&g_S[((size_t)tt * B_ + bb) * CW + c0 + tx * 4] = v;
    }
}

// ---------------- kernel 3: recurrence (4-CTA cluster, resident fp32 weights) ----------
// 256 threads, R1 layout (at the weight-wavefront floor): jl = tid>>2 (8 jl/warp ->
// 128B/instr weight loads), bg = tid&3 (4 h-lines/instr), full k=256 per thread,
// 2 batches per thread. R2 additions kept: register-prefetched S, vectorized dh
// scale, float4 DSMEM exchange.
__global__ void __cluster_dims__(4, 1, 1) __launch_bounds__(256, 1) recur_kernel() {
    extern __shared__ float smem[];
    float* Wq    = smem;                       // [3][64][WPAD]
    float* hbuf  = Wq + 3 * 64 * WPAD;         // [NB][WPAD]  layout [b][k]
    float* rhbuf = hbuf + NB * WPAD;           // [NB][WPAD]

    cg::cluster_group cluster = cg::this_cluster();
    const int rank = (int)cluster.block_rank();    // 0..3, owns j in [rank*64, rank*64+64)
    const int tid  = threadIdx.x;
    const int jl   = tid >> 2;                     // 0..63
    const int bg   = tid & 3;
    const int b0   = bg, b1 = bg + 4;              // 2 batches per thread
    const int jg   = rank * 64 + jl;
    const int b_base = (blockIdx.x >> 2) * NB;
    const int b_s  = tid >> 5;                     // scale role: batch 0..7
    const int k8s  = (tid & 31) * 8;               // scale role: 8 k per thread

    // Load this CTA's j-slice of the 3 recurrent matrices (float4, coalesced)
    for (int idx4 = tid; idx4 < 3 * 64 * 64; idx4 += 256) {
        int g  = idx4 >> 12;
        int jj = (idx4 >> 6) & 63;
        int kq = idx4 & 63;
        float4 v = *(const float4*)&g_WT[g * 65536 + (rank * 64 + jj) * 256 + kq * 4];
        *(float4*)&Wq[g * (64 * WPAD) + jj * WPAD + kq * 4] = v;
    }
    for (int i = tid; i < NB * WPAD; i += 256) { hbuf[i] = 0.f; rhbuf[i] = 0.f; }
    __syncthreads();
    cluster.sync();

    const float* wzp = Wq + jl * WPAD;
    const float* wrp = Wq + 64 * WPAD + jl * WPAD;
    const float* whp = Wq + 2 * 64 * WPAD + jl * WPAD;
    const float* h0p = hbuf + b0 * WPAD;
    const float* h1p = hbuf + b1 * WPAD;
    const float* p0p = rhbuf + b0 * WPAD;
    const float* p1p = rhbuf + b1 * WPAD;

    // preload t=0 S values
    size_t srow0 = (size_t)(b_base + b0) * CW;
    size_t srow1 = (size_t)(b_base + b1) * CW;
    float az0c = g_S[srow0 + jg],        az1c = g_S[srow1 + jg];
    float ar0c = g_S[srow0 + 256 + jg],  ar1c = g_S[srow1 + 256 + jg];
    float ah0c = g_S[srow0 + 512 + jg],  ah1c = g_S[srow1 + 512 + jg];
    float4 dhcA = *(const float4*)&g_S[(size_t)(b_base + b_s) * CW + 768 + k8s];
    float4 dhcB = *(const float4*)&g_S[(size_t)(b_base + b_s) * CW + 768 + k8s + 4];

    for (int t = 0; t < T_; t++) {
        // ---- scale h by delta_h (prefetched; 8 k per thread, vectorized) ----
        {
            float4 ha = *(float4*)&hbuf[b_s * WPAD + k8s];
            float4 hb = *(float4*)&hbuf[b_s * WPAD + k8s + 4];
            ha.x *= dhcA.x; ha.y *= dhcA.y; ha.z *= dhcA.z; ha.w *= dhcA.w;
            hb.x *= dhcB.x; hb.y *= dhcB.y; hb.z *= dhcB.z; hb.w *= dhcB.w;
            *(float4*)&hbuf[b_s * WPAD + k8s]     = ha;
            *(float4*)&hbuf[b_s * WPAD + k8s + 4] = hb;
        }
        __syncthreads();

        // ---- prefetch t+1 S values (consumed next iteration; hidden under matvecs) ----
        int tn = (t + 1 < T_) ? t + 1 : t;
        size_t nrow0 = ((size_t)tn * B_ + b_base + b0) * CW;
        size_t nrow1 = ((size_t)tn * B_ + b_base + b1) * CW;
        float naz0 = g_S[nrow0 + jg],       naz1 = g_S[nrow1 + jg];
        float nar0 = g_S[nrow0 + 256 + jg], nar1 = g_S[nrow1 + 256 + jg];
        float nah0 = g_S[nrow0 + 512 + jg], nah1 = g_S[nrow1 + 512 + jg];
        float4 ndhA = *(const float4*)&g_S[((size_t)tn * B_ + b_base + b_s) * CW + 768 + k8s];
        float4 ndhB = *(const float4*)&g_S[((size_t)tn * B_ + b_base + b_s) * CW + 768 + k8s + 4];

        float hj0 = h0p[jg];
        float hj1 = h1p[jg];

        // ---- z / r matvecs over full k=256 ----
        float accz0 = 0.f, accz1 = 0.f, accr0 = 0.f, accr1 = 0.f;
#pragma unroll 8
        for (int kk = 0; kk < 256; kk += 4) {
            float4 wz = *(const float4*)&wzp[kk];
            float4 wr = *(const float4*)&wrp[kk];
            float4 h0 = *(const float4*)&h0p[kk];
            float4 h1 = *(const float4*)&h1p[kk];
            accz0 = fmaf(wz.x,h0.x, fmaf(wz.y,h0.y, fmaf(wz.z,h0.z, fmaf(wz.w,h0.w, accz0))));
            accz1 = fmaf(wz.x,h1.x, fmaf(wz.y,h1.y, fmaf(wz.z,h1.z, fmaf(wz.w,h1.w, accz1))));
            accr0 = fmaf(wr.x,h0.x, fmaf(wr.y,h0.y, fmaf(wr.z,h0.z, fmaf(wr.w,h0.w, accr0))));
            accr1 = fmaf(wr.x,h1.x, fmaf(wr.y,h1.y, fmaf(wr.z,h1.z, fmaf(wr.w,h1.w, accr1))));
        }
        float z0 = sigf(accz0 + az0c);
        float z1 = sigf(accz1 + az1c);
        float r0 = sigf(accr0 + ar0c);
        float r1 = sigf(accr1 + ar1c);

        rhbuf[b0 * WPAD + jg] = r0 * hj0;
        rhbuf[b1 * WPAD + jg] = r1 * hj1;
        __syncthreads();
        // push my contiguous j-quarter of rh to the 3 peers (float4 blocks)
#pragma unroll
        for (int base = 0; base < 384; base += 256) {
            int idx = base + tid;
            if (idx < 384) {
                int pr   = idx >> 7;                    // 0..2
                int peer = (rank + 1 + pr) & 3;
                int rem  = idx & 127;
                int bb   = rem >> 4;
                int v    = rem & 15;
                int off  = bb * WPAD + rank * 64 + v * 4;
                float4 val = *(float4*)&rhbuf[off];
                float* dst = cluster.map_shared_rank(rhbuf, peer);
                *(float4*)&dst[off] = val;
            }
        }
        cluster.sync();

        // ---- h_tilde matvec over full r*h ----
        float acch0 = 0.f, acch1 = 0.f;
#pragma unroll 8
        for (int kk = 0; kk < 256; kk += 4) {
            float4 wh = *(const float4*)&whp[kk];
            float4 p0 = *(const float4*)&p0p[kk];
            float4 p1 = *(const float4*)&p1p[kk];
            acch0 = fmaf(wh.x,p0.x, fmaf(wh.y,p0.y, fmaf(wh.z,p0.z, fmaf(wh.w,p0.w, acch0))));
            acch1 = fmaf(wh.x,p1.x, fmaf(wh.y,p1.y, fmaf(wh.z,p1.z, fmaf(wh.w,p1.w, acch1))));
        }
        float ht0 = tanhf(acch0 + ah0c);
        float ht1 = tanhf(acch1 + ah1c);
        float hn0 = (1.f - z0) * hj0 + z0 * ht0;
        float hn1 = (1.f - z1) * hj1 + z1 * ht1;
        hbuf[b0 * WPAD + jg] = hn0;
        hbuf[b1 * WPAD + jg] = hn1;
        __syncthreads();
#pragma unroll
        for (int base = 0; base < 384; base += 256) {
            int idx = base + tid;
            if (idx < 384) {
                int pr   = idx >> 7;
                int peer = (rank + 1 + pr) & 3;
                int rem  = idx & 127;
                int bb   = rem >> 4;
                int v    = rem & 15;
                int off  = bb * WPAD + rank * 64 + v * 4;
                float4 val = *(float4*)&hbuf[off];
                float* dst = cluster.map_shared_rank(hbuf, peer);
                *(float4*)&dst[off] = val;
            }
        }
        cluster.sync();

        if (t == T_ - 1) {
            g_Hfin[(b_base + b0) * H_ + jg] = hn0;
            g_Hfin[(b_base + b1) * H_ + jg] = hn1;
        }
        az0c = naz0; az1c = naz1; ar0c = nar0; ar1c = nar1;
        ah0c = nah0; ah1c = nah1; dhcA = ndhA; dhcB = ndhB;
    }
}

// ---------------- kernel 4: out = h_final @ W_out^T + b_out ----------------
__global__ void finalize_k(const float* __restrict__ Wout, const float* __restrict__ bout,
                           float* __restrict__ out) {
    int b = blockIdx.x;
    int tid = threadIdx.x;   // 64 threads
    float s = 0.f;
    for (int j = tid; j < H_; j += 64) s += g_Hfin[b * H_ + j] * Wout[j];
    __shared__ float red[64];
    red[tid] = s;
    __syncthreads();
    if (tid < 32) {
        float v = red[tid] + red[tid + 32];
#pragma unroll
        for (int o = 16; o; o >>= 1) v += __shfl_down_sync(0xffffffffu, v, o);
        if (tid == 0) out[b] = v + bout[0];
    }
}

// ---------------- host launcher ----------------
extern "C" void kernel_launch(void* const* d_in, const int* in_sizes, int n_in,
                              void* d_out, int out_size) {
    const float* inp   = (const float*)d_in[0];
    // d_in[1] = static_data (unused by the reference computation)
    const float* Xmean = (const float*)d_in[2];
    const float* Wz    = (const float*)d_in[3];
    const float* bz    = (const float*)d_in[4];
    const float* Wr    = (const float*)d_in[5];
    const float* br    = (const float*)d_in[6];
    const float* Wh    = (const float*)d_in[7];
    const float* bh    = (const float*)d_in[8];
    const float* Wgx   = (const float*)d_in[9];
    const float* bgx   = (const float*)d_in[10];
    const float* Wgh   = (const float*)d_in[11];
    const float* bgh   = (const float*)d_in[12];
    const float* Wout  = (const float*)d_in[13];
    const float* bout  = (const float*)d_in[14];
    float* out = (float*)d_out;

    pack_kernel<<<(CW * KU + 255) / 256, 256>>>(Wz, bz, Wr, br, Wh, bh, Wgh, bgh);
    build_U<<<(R_ * D_ + 255) / 256, 256>>>(inp, Xmean, Wgx, bgx);

    dim3 g2(CW / 64, R_ / 128);   // 16 x 512 tiles
    gemm_pre<<<g2, 256>>>();

    const int smemb = (3 * 64 * WPAD + 2 * NB * WPAD) * (int)sizeof(float);  // 216320 B
    cudaFuncSetAttribute(recur_kernel, cudaFuncAttributeMaxDynamicSharedMemorySize, smemb);
    recur_kernel<<<128, 256, smemb>>>();   // 32 clusters of 4 CTAs

    finalize_k<<<B_, 64>>>(Wout, bout, out);
}